// round 1
// baseline (speedup 1.0000x reference)
#include <cuda_runtime.h>
#include <math.h>

// ---------------------------------------------------------------------------
// BatchShapingLoss: x (512,128) f32 -> scalar loss
//   sorted = sort(x, axis=0)
//   t_k = EPS + k/999 * (s - EPS), k = 1..999   (k=0 dropped: pdf0 > 1)
//   pdf(t) = exp((a-1) ln t + (b-1) ln(1-t) - Bln),  a=0.6, b=0.4
//   pcdf = trapezoid(pdf, t)  = h * (sum_{1..999} p_k - 0.5 p_1 - 0.5 p_999)
//   loss = sum((pcdf - (rank+1)/513)^2) / 512
//
// Trick: log2(t_k) ~= log2(k) + log2(h)  (EPS negligible vs t_1), so the
// log2(k) factor is a shared 999-entry SMEM table -> 2 MUFU per eval.
// ---------------------------------------------------------------------------

#define NROWS 512
#define NCOLS 128
#define EPSV  1e-10f

static __device__ __forceinline__ float lg2f(float x) {
    float r; asm("lg2.approx.f32 %0, %1;" : "=f"(r) : "f"(x)); return r;
}
static __device__ __forceinline__ float ex2f(float x) {
    float r; asm("ex2.approx.f32 %0, %1;" : "=f"(r) : "f"(x)); return r;
}

__device__ float g_sorted[NROWS * NCOLS];   // column-major: [c*512 + n]
__device__ float g_partials[1024];

// ---- per-column bitonic sort: 128 blocks x 512 threads ----
__global__ void __launch_bounds__(512) sort_cols(const float* __restrict__ x) {
    __shared__ float s[NROWS];
    int tid = threadIdx.x;
    int c = blockIdx.x;
    s[tid] = x[tid * NCOLS + c];
    __syncthreads();
    for (int k = 2; k <= NROWS; k <<= 1) {
        for (int j = k >> 1; j > 0; j >>= 1) {
            int ixj = tid ^ j;
            if (ixj > tid) {
                float a = s[tid], b = s[ixj];
                bool up = ((tid & k) == 0);
                if ((a > b) == up) { s[tid] = b; s[ixj] = a; }
            }
            __syncthreads();
        }
    }
    g_sorted[c * NROWS + tid] = s[tid];
}

// ---- main quadrature: 1024 blocks x 256 threads ----
// Each block handles 64 elements; each element's 999-point sum is split
// across 4 chunks (one per 64-thread group -> warp-uniform table index).
__global__ void __launch_bounds__(256) quad_kernel(float c2 /* BETALN/ln2 */) {
    __shared__ float tab[1000];        // tab[k] = -0.4 * log2(k)
    __shared__ float csum[4][64];
    __shared__ float wsum[8];

    const float A1 = -0.4f;            // alpha - 1
    const float B1 = -0.6f;            // beta  - 1

    int tid = threadIdx.x;
    for (int k = tid; k < 1000; k += 256)
        tab[k] = (k > 0) ? A1 * lg2f((float)k) : 0.0f;
    __syncthreads();

    int chunk = tid >> 6;              // 0..3, uniform per warp-pair
    int el    = tid & 63;
    int e     = blockIdx.x * 64 + el;  // e = c*512 + n (column-major)

    float s    = g_sorted[e];
    float h    = (s - EPSV) * (1.0f / 999.0f);
    float base = fmaf(A1, lg2f(h), -c2);   // -0.4*log2(h) - BETALN/ln2

    int   k0    = 1 + chunk * 250;          // chunks: 1-250,251-500,501-750,751-999
    int   niter = (chunk == 3) ? 249 : 250;
    float kf    = (float)k0;
    float acc   = 0.0f;
    const float* tptr = tab + k0;

    #pragma unroll 5
    for (int i = 0; i < niter; i++) {
        float t   = fmaf(kf, h, EPSV);
        float l   = lg2f(1.0f - t);
        float arg = fmaf(B1, l, base + tptr[i]);
        acc += ex2f(arg);
        kf += 1.0f;
    }

    csum[chunk][el] = acc;
    __syncthreads();

    float sq = 0.0f;
    if (tid < 64) {                    // chunk 0 thread: its own h/base are valid for element e
        float S = csum[0][el] + csum[1][el] + csum[2][el] + csum[3][el];
        // trapezoid endpoint corrections (exact evals, negligible cost)
        float t1   = fmaf(1.0f, h, EPSV);
        float p1   = ex2f(fmaf(B1, lg2f(1.0f - t1), base + tab[1]));
        float t9   = fmaf(999.0f, h, EPSV);
        float p999 = ex2f(fmaf(B1, lg2f(1.0f - t9), base + tab[999]));
        float pcdf = h * (S - 0.5f * (p1 + p999));
        int   n    = e & (NROWS - 1);
        float ecdf = (float)(n + 1) * (1.0f / 513.0f);
        float d    = pcdf - ecdf;
        sq = d * d;
    }

    // deterministic block reduction
    #pragma unroll
    for (int o = 16; o > 0; o >>= 1)
        sq += __shfl_xor_sync(0xffffffffu, sq, o);
    if ((tid & 31) == 0) wsum[tid >> 5] = sq;
    __syncthreads();
    if (tid == 0) {
        float t = wsum[0] + wsum[1] + wsum[2] + wsum[3]
                + wsum[4] + wsum[5] + wsum[6] + wsum[7];
        g_partials[blockIdx.x] = t;
    }
}

// ---- final deterministic reduction ----
__global__ void __launch_bounds__(256) reduce_kernel(float* __restrict__ out) {
    __shared__ float w[8];
    int tid = threadIdx.x;
    float v = g_partials[tid] + g_partials[tid + 256]
            + g_partials[tid + 512] + g_partials[tid + 768];
    #pragma unroll
    for (int o = 16; o > 0; o >>= 1)
        v += __shfl_xor_sync(0xffffffffu, v, o);
    if ((tid & 31) == 0) w[tid >> 5] = v;
    __syncthreads();
    if (tid == 0) {
        float t = w[0] + w[1] + w[2] + w[3] + w[4] + w[5] + w[6] + w[7];
        out[0] = t * (1.0f / (float)NROWS);
    }
}

extern "C" void kernel_launch(void* const* d_in, const int* in_sizes, int n_in,
                              void* d_out, int out_size) {
    const float* x = (const float*)d_in[0];
    // BETALN computed with the same libm lgamma the Python reference uses
    double betaln = lgamma(0.6) + lgamma(0.4) - lgamma(1.0);
    float  c2 = (float)(betaln * 1.4426950408889634);  // BETALN / ln(2)

    sort_cols<<<128, 512>>>(x);
    quad_kernel<<<1024, 256>>>(c2);
    reduce_kernel<<<1, 256>>>((float*)d_out);
}